// round 2
// baseline (speedup 1.0000x reference)
#include <cuda_runtime.h>
#include <cuda_bf16.h>
#include <cstdint>

#define NQ 16384
#define NK 16384
#define DIM 256
#define DV 256

// ---------------- scratch: bf16 hi/lo splits (48 MB static device arrays) ----------------
__device__ __nv_bfloat16 g_Qh[NQ * DIM];
__device__ __nv_bfloat16 g_Ql[NQ * DIM];
__device__ __nv_bfloat16 g_Kh[NK * DIM];
__device__ __nv_bfloat16 g_Kl[NK * DIM];
__device__ __nv_bfloat16 g_Vh[NK * DV];
__device__ __nv_bfloat16 g_Vl[NK * DV];

// ---------------- helpers ----------------
__device__ __forceinline__ unsigned smem_u32(const void* p) {
    return (unsigned)__cvta_generic_to_shared(p);
}

__device__ __forceinline__ void ldsm_x4(uint32_t* r, unsigned addr) {
    asm volatile("ldmatrix.sync.aligned.m8n8.x4.shared.b16 {%0,%1,%2,%3}, [%4];"
                 : "=r"(r[0]), "=r"(r[1]), "=r"(r[2]), "=r"(r[3]) : "r"(addr));
}
__device__ __forceinline__ void ldsm_x2(uint32_t* r, unsigned addr) {
    asm volatile("ldmatrix.sync.aligned.m8n8.x2.shared.b16 {%0,%1}, [%2];"
                 : "=r"(r[0]), "=r"(r[1]) : "r"(addr));
}
__device__ __forceinline__ void ldsm_x2_trans(uint32_t* r, unsigned addr) {
    asm volatile("ldmatrix.sync.aligned.m8n8.x2.trans.shared.b16 {%0,%1}, [%2];"
                 : "=r"(r[0]), "=r"(r[1]) : "r"(addr));
}
__device__ __forceinline__ void mma_bf16(float* c, const uint32_t* a, const uint32_t* b) {
    asm volatile(
        "mma.sync.aligned.m16n8k16.row.col.f32.bf16.bf16.f32 "
        "{%0,%1,%2,%3},{%4,%5,%6,%7},{%8,%9},{%0,%1,%2,%3};"
        : "+f"(c[0]), "+f"(c[1]), "+f"(c[2]), "+f"(c[3])
        : "r"(a[0]), "r"(a[1]), "r"(a[2]), "r"(a[3]), "r"(b[0]), "r"(b[1]));
}

// ---------------- kernel 1: fp32 -> bf16 hi/lo splits ----------------
__global__ void split_all_kernel(const float* __restrict__ Q,
                                 const float* __restrict__ K,
                                 const float* __restrict__ V) {
    int i = blockIdx.x * blockDim.x + threadIdx.x;
    if (i < NQ * DIM) {
        float q = Q[i];
        __nv_bfloat16 qh = __float2bfloat16(q);
        g_Qh[i] = qh;
        g_Ql[i] = __float2bfloat16(q - __bfloat162float(qh));
        float k = K[i];
        __nv_bfloat16 kh = __float2bfloat16(k);
        g_Kh[i] = kh;
        g_Kl[i] = __float2bfloat16(k - __bfloat162float(kh));
        float v = V[i];
        __nv_bfloat16 vh = __float2bfloat16(v);
        g_Vh[i] = vh;
        g_Vl[i] = __float2bfloat16(v - __bfloat162float(vh));
    }
}

// ---------------- kernel 2: S = Q K^T (unnormalized scores into W region) ----------------
// CTA tile 128x128, K-chunks of 64, 8 warps laid out 2(m) x 4(n); warp tile 64x32.
// Error-compensated bf16: S = Qh*Kh + Qh*Kl + Ql*Kh.
#define QKS 72  // smem row stride in bf16 elems (64 + 8 pad; 144B rows, ldmatrix conflict-free)

__global__ __launch_bounds__(256, 1) void qk_kernel(float* __restrict__ W) {
    extern __shared__ __nv_bfloat16 sm[];
    __nv_bfloat16* sQh = sm;
    __nv_bfloat16* sQl = sm + 128 * QKS;
    __nv_bfloat16* sKh = sm + 2 * 128 * QKS;
    __nv_bfloat16* sKl = sm + 3 * 128 * QKS;

    const int tid = threadIdx.x;
    const int lane = tid & 31, w = tid >> 5;
    const int wm = w >> 2, wn = w & 3;
    const int qBase = blockIdx.y * 128;
    const int kBase = blockIdx.x * 128;

    float acc[4][4][4];
#pragma unroll
    for (int mi = 0; mi < 4; mi++)
#pragma unroll
        for (int ni = 0; ni < 4; ni++)
#pragma unroll
            for (int j = 0; j < 4; j++) acc[mi][ni][j] = 0.f;

    for (int kc = 0; kc < DIM; kc += 64) {
        // load 128x64 chunks of Qh/Ql/Kh/Kl into smem (uint4 = 8 bf16)
#pragma unroll
        for (int it = 0; it < 4; it++) {
            int idx = it * 256 + tid;
            int row = idx >> 3, cv = (idx & 7) << 3;
            *(uint4*)&sQh[row * QKS + cv] =
                *(const uint4*)&g_Qh[(size_t)(qBase + row) * DIM + kc + cv];
            *(uint4*)&sQl[row * QKS + cv] =
                *(const uint4*)&g_Ql[(size_t)(qBase + row) * DIM + kc + cv];
            *(uint4*)&sKh[row * QKS + cv] =
                *(const uint4*)&g_Kh[(size_t)(kBase + row) * DIM + kc + cv];
            *(uint4*)&sKl[row * QKS + cv] =
                *(const uint4*)&g_Kl[(size_t)(kBase + row) * DIM + kc + cv];
        }
        __syncthreads();

#pragma unroll
        for (int ks = 0; ks < 4; ks++) {
            const int k0 = ks * 16;
            uint32_t ah[4][4], al[4][4], bh[4][2], bl[4][2];
#pragma unroll
            for (int mi = 0; mi < 4; mi++) {
                int m0 = wm * 64 + mi * 16;
                int mat = lane >> 3;
                int r = m0 + ((mat & 1) << 3) + (lane & 7);
                int c = k0 + ((mat >> 1) << 3);
                ldsm_x4(ah[mi], smem_u32(&sQh[r * QKS + c]));
                ldsm_x4(al[mi], smem_u32(&sQl[r * QKS + c]));
            }
#pragma unroll
            for (int ni = 0; ni < 4; ni++) {
                int n0 = wn * 32 + ni * 8;
                int mat = (lane >> 3) & 1;
                int r = n0 + (lane & 7);
                int c = k0 + (mat << 3);
                ldsm_x2(bh[ni], smem_u32(&sKh[r * QKS + c]));
                ldsm_x2(bl[ni], smem_u32(&sKl[r * QKS + c]));
            }
#pragma unroll
            for (int mi = 0; mi < 4; mi++)
#pragma unroll
                for (int ni = 0; ni < 4; ni++) {
                    mma_bf16(acc[mi][ni], ah[mi], bh[ni]);
                    mma_bf16(acc[mi][ni], ah[mi], bl[ni]);
                    mma_bf16(acc[mi][ni], al[mi], bh[ni]);
                }
        }
        __syncthreads();
    }

#pragma unroll
    for (int mi = 0; mi < 4; mi++) {
        int r0 = qBase + wm * 64 + mi * 16 + (lane >> 2);
#pragma unroll
        for (int ni = 0; ni < 4; ni++) {
            int c0 = kBase + wn * 32 + ni * 8 + ((lane & 3) << 1);
            *(float2*)&W[(size_t)r0 * NK + c0] = make_float2(acc[mi][ni][0], acc[mi][ni][1]);
            *(float2*)&W[(size_t)(r0 + 8) * NK + c0] = make_float2(acc[mi][ni][2], acc[mi][ni][3]);
        }
    }
}

// ---------------- kernel 3: in-place row softmax on W ----------------
// One CTA per row; 16384 floats (64KB) cached in dynamic smem.
__global__ __launch_bounds__(256, 1) void softmax_kernel(float* __restrict__ W) {
    extern __shared__ float rowbuf[];
    __shared__ float red[8];
    const int tid = threadIdx.x;
    const int lane = tid & 31, w = tid >> 5;
    float4* Wr = (float4*)(W + (size_t)blockIdx.x * NK);
    float4* R = (float4*)rowbuf;

    float lmax = -3.0e38f;
#pragma unroll
    for (int i = 0; i < 16; i++) {
        int idx = i * 256 + tid;
        float4 t = Wr[idx];
        R[idx] = t;
        lmax = fmaxf(lmax, fmaxf(fmaxf(t.x, t.y), fmaxf(t.z, t.w)));
    }
#pragma unroll
    for (int o = 16; o; o >>= 1) lmax = fmaxf(lmax, __shfl_xor_sync(0xffffffffu, lmax, o));
    if (lane == 0) red[w] = lmax;
    __syncthreads();
    float mx = red[0];
#pragma unroll
    for (int j = 1; j < 8; j++) mx = fmaxf(mx, red[j]);
    __syncthreads();

    float lsum = 0.f;
#pragma unroll
    for (int i = 0; i < 16; i++) {
        int idx = i * 256 + tid;
        float4 t = R[idx];
        t.x = __expf(t.x - mx);
        t.y = __expf(t.y - mx);
        t.z = __expf(t.z - mx);
        t.w = __expf(t.w - mx);
        R[idx] = t;
        lsum += t.x + t.y + t.z + t.w;
    }
#pragma unroll
    for (int o = 16; o; o >>= 1) lsum += __shfl_xor_sync(0xffffffffu, lsum, o);
    if (lane == 0) red[w] = lsum;
    __syncthreads();
    float total = 0.f;
#pragma unroll
    for (int j = 0; j < 8; j++) total += red[j];
    float inv = 1.0f / total;

#pragma unroll
    for (int i = 0; i < 16; i++) {
        int idx = i * 256 + tid;
        float4 t = R[idx];
        t.x *= inv; t.y *= inv; t.z *= inv; t.w *= inv;
        Wr[idx] = t;
    }
}

// ---------------- kernel 4: X = W V ----------------
// CTA tile 64(m) x 256(n), K-chunks of 64. Warps 2(m) x 4(n); warp tile 32x64.
// W fp32 tiles are split into bf16 hi/lo in-kernel; V hi/lo precomputed.
__global__ __launch_bounds__(256, 1) void pv_kernel(const float* __restrict__ W,
                                                    float* __restrict__ X) {
    extern __shared__ __nv_bfloat16 sm[];
    __nv_bfloat16* sWh = sm;                       // 64 x 72
    __nv_bfloat16* sWl = sm + 64 * 72;             // 64 x 72
    __nv_bfloat16* sVh = sm + 2 * 64 * 72;         // 64 x 264
    __nv_bfloat16* sVl = sm + 2 * 64 * 72 + 64 * 264;

    const int tid = threadIdx.x;
    const int lane = tid & 31, w = tid >> 5;
    const int wm = w >> 2, wn = w & 3;
    const int mBase = blockIdx.x * 64;

    float acc[2][8][4];
#pragma unroll
    for (int mi = 0; mi < 2; mi++)
#pragma unroll
        for (int ni = 0; ni < 8; ni++)
#pragma unroll
            for (int j = 0; j < 4; j++) acc[mi][ni][j] = 0.f;

    for (int k0 = 0; k0 < NK; k0 += 64) {
        // W chunk 64x64 fp32 -> bf16 hi/lo in smem
#pragma unroll
        for (int it = 0; it < 4; it++) {
            int idx = it * 256 + tid;
            int row = idx >> 4, cv = (idx & 15) << 2;
            float4 t = *(const float4*)&W[(size_t)(mBase + row) * NK + k0 + cv];
            __nv_bfloat16 h0 = __float2bfloat16(t.x), h1 = __float2bfloat16(t.y);
            __nv_bfloat16 h2 = __float2bfloat16(t.z), h3 = __float2bfloat16(t.w);
            __nv_bfloat16 l0 = __float2bfloat16(t.x - __bfloat162float(h0));
            __nv_bfloat16 l1 = __float2bfloat16(t.y - __bfloat162float(h1));
            __nv_bfloat16 l2 = __float2bfloat16(t.z - __bfloat162float(h2));
            __nv_bfloat16 l3 = __float2bfloat16(t.w - __bfloat162float(h3));
            __nv_bfloat162* ph = (__nv_bfloat162*)&sWh[row * 72 + cv];
            ph[0] = __halves2bfloat162(h0, h1);
            ph[1] = __halves2bfloat162(h2, h3);
            __nv_bfloat162* pl = (__nv_bfloat162*)&sWl[row * 72 + cv];
            pl[0] = __halves2bfloat162(l0, l1);
            pl[1] = __halves2bfloat162(l2, l3);
        }
        // V chunk 64x256 (hi and lo)
#pragma unroll
        for (int it = 0; it < 8; it++) {
            int idx = it * 256 + tid;
            int row = idx >> 5, cv = (idx & 31) << 3;
            *(uint4*)&sVh[row * 264 + cv] =
                *(const uint4*)&g_Vh[(size_t)(k0 + row) * DV + cv];
            *(uint4*)&sVl[row * 264 + cv] =
                *(const uint4*)&g_Vl[(size_t)(k0 + row) * DV + cv];
        }
        __syncthreads();

#pragma unroll
        for (int ks = 0; ks < 4; ks++) {
            int kk = ks * 16;
            uint32_t ah[2][4], al[2][4], bh[8][2], bl[8][2];
#pragma unroll
            for (int mi = 0; mi < 2; mi++) {
                int m0 = wm * 32 + mi * 16;
                int mat = lane >> 3;
                int r = m0 + ((mat & 1) << 3) + (lane & 7);
                int c = kk + ((mat >> 1) << 3);
                ldsm_x4(ah[mi], smem_u32(&sWh[r * 72 + c]));
                ldsm_x4(al[mi], smem_u32(&sWl[r * 72 + c]));
            }
#pragma unroll
            for (int ni = 0; ni < 8; ni++) {
                int n0 = wn * 64 + ni * 8;
                int mat = (lane >> 3) & 1;
                int r = kk + (mat << 3) + (lane & 7);
                ldsm_x2_trans(bh[ni], smem_u32(&sVh[r * 264 + n0]));
                ldsm_x2_trans(bl[ni], smem_u32(&sVl[r * 264 + n0]));
            }
#pragma unroll
            for (int mi = 0; mi < 2; mi++)
#pragma unroll
                for (int ni = 0; ni < 8; ni++) {
                    mma_bf16(acc[mi][ni], ah[mi], bh[ni]);
                    mma_bf16(acc[mi][ni], ah[mi], bl[ni]);
                    mma_bf16(acc[mi][ni], al[mi], bh[ni]);
                }
        }
        __syncthreads();
    }

#pragma unroll
    for (int mi = 0; mi < 2; mi++) {
        int r0 = mBase + wm * 32 + mi * 16 + (lane >> 2);
#pragma unroll
        for (int ni = 0; ni < 8; ni++) {
            int c0 = wn * 64 + ni * 8 + ((lane & 3) << 1);
            *(float2*)&X[(size_t)r0 * DV + c0] = make_float2(acc[mi][ni][0], acc[mi][ni][1]);
            *(float2*)&X[(size_t)(r0 + 8) * DV + c0] = make_float2(acc[mi][ni][2], acc[mi][ni][3]);
        }
    }
}

// ---------------- launcher ----------------
extern "C" void kernel_launch(void* const* d_in, const int* in_sizes, int n_in,
                              void* d_out, int out_size) {
    const float* Q = (const float*)d_in[0];
    const float* K = (const float*)d_in[1];
    const float* V = (const float*)d_in[2];
    float* X = (float*)d_out;                       // [NQ, DV] first
    float* W = (float*)d_out + (size_t)NQ * DV;     // [NQ, NK] second

    const int qk_smem = 4 * 128 * QKS * 2;                      // 73728 B
    const int sm_smem = NK * 4;                                 // 65536 B
    const int pv_smem = (2 * 64 * 72 + 2 * 64 * 264) * 2;       // 86016 B
    cudaFuncSetAttribute(qk_kernel, cudaFuncAttributeMaxDynamicSharedMemorySize, qk_smem);
    cudaFuncSetAttribute(softmax_kernel, cudaFuncAttributeMaxDynamicSharedMemorySize, sm_smem);
    cudaFuncSetAttribute(pv_kernel, cudaFuncAttributeMaxDynamicSharedMemorySize, pv_smem);

    split_all_kernel<<<(NQ * DIM + 255) / 256, 256>>>(Q, K, V);

    dim3 qkGrid(NK / 128, NQ / 128);
    qk_kernel<<<qkGrid, 256, qk_smem>>>(W);

    softmax_kernel<<<NQ, 256, sm_smem>>>(W);

    pv_kernel<<<NQ / 64, 256, pv_smem>>>(W, X);
}